// round 1
// baseline (speedup 1.0000x reference)
#include <cuda_runtime.h>
#include <mma.h>
using namespace nvcuda;

// SimpleRelativeAttention collapses algebraically:
//   einsum('bnqk,bnqe->bnqe', softmax(attn), v) = rowsum(softmax) * v = v
// => out = x @ (Wv @ Wproj) + (b_v @ Wproj + b_proj),  Wv = w_qkv[:, 2048:3072]

constexpr int DIMC  = 1024;
constexpr int BATCH = 4;
constexpr int SEQ   = 1024;
constexpr int MX    = BATCH * SEQ;   // 4096

__device__ float g_wc[DIMC * DIMC];  // combined weight W' = Wv @ Wproj
__device__ float g_bc[DIMC];         // combined bias

constexpr int BM = 128, BN = 128, BK = 32;
constexpr int WM = 64,  WN = 32;     // 2x4 warp grid, 8 warps

// C[M,N] = A[M,K](lda) @ B[K,N](ldb) (+ bias per column), tf32 tensor cores.
// M,N multiples of 128; K multiple of 32. Grid: (N/BN, M/BM), 256 threads.
__global__ __launch_bounds__(256) void gemm_tf32(
    const float* __restrict__ A, int lda,
    const float* __restrict__ B, int ldb,
    float* __restrict__ C, int ldc,
    const float* __restrict__ bias,
    int K)
{
    __shared__ float As[BM][BK + 4];   // 128 x 36
    __shared__ float Bs[BK][BN + 4];   // 32 x 132

    const int tid  = threadIdx.x;
    const int wid  = tid >> 5;
    const int lane = tid & 31;
    const int wrow = wid >> 2;         // 0..1
    const int wcol = wid & 3;          // 0..3
    const int bm   = blockIdx.y * BM;
    const int bn   = blockIdx.x * BN;

    wmma::fragment<wmma::accumulator, 16, 16, 8, float> c[4][2];
#pragma unroll
    for (int i = 0; i < 4; i++)
#pragma unroll
        for (int j = 0; j < 2; j++)
            wmma::fill_fragment(c[i][j], 0.0f);

    for (int k0 = 0; k0 < K; k0 += BK) {
        // Load A tile 128x32 (8 float4 per row)
#pragma unroll
        for (int i = 0; i < 4; i++) {
            int v  = tid + i * 256;
            int r  = v >> 3;
            int cv = (v & 7) << 2;
            float4 t = *reinterpret_cast<const float4*>(&A[(size_t)(bm + r) * lda + k0 + cv]);
            *reinterpret_cast<float4*>(&As[r][cv]) = t;
        }
        // Load B tile 32x128 (32 float4 per row)
#pragma unroll
        for (int i = 0; i < 4; i++) {
            int v  = tid + i * 256;
            int r  = v >> 5;
            int cv = (v & 31) << 2;
            float4 t = *reinterpret_cast<const float4*>(&B[(size_t)(k0 + r) * ldb + bn + cv]);
            *reinterpret_cast<float4*>(&Bs[r][cv]) = t;
        }
        __syncthreads();

#pragma unroll
        for (int kk = 0; kk < BK / 8; kk++) {
            wmma::fragment<wmma::matrix_a, 16, 16, 8, wmma::precision::tf32, wmma::row_major> a[4];
            wmma::fragment<wmma::matrix_b, 16, 16, 8, wmma::precision::tf32, wmma::row_major> b[2];
#pragma unroll
            for (int i = 0; i < 4; i++) {
                wmma::load_matrix_sync(a[i], &As[wrow * WM + i * 16][kk * 8], BK + 4);
#pragma unroll
                for (int t = 0; t < a[i].num_elements; t++)
                    a[i].x[t] = wmma::__float_to_tf32(a[i].x[t]);
            }
#pragma unroll
            for (int j = 0; j < 2; j++) {
                wmma::load_matrix_sync(b[j], &Bs[kk * 8][wcol * WN + j * 16], BN + 4);
#pragma unroll
                for (int t = 0; t < b[j].num_elements; t++)
                    b[j].x[t] = wmma::__float_to_tf32(b[j].x[t]);
            }
#pragma unroll
            for (int i = 0; i < 4; i++)
#pragma unroll
                for (int j = 0; j < 2; j++)
                    wmma::mma_sync(c[i][j], a[i], b[j], c[i][j]);
        }
        __syncthreads();
    }

    // Epilogue: per-warp smem staging (reuse As), bias add, vectorized store.
    float* stage = &As[0][0] + wid * (16 * 20);  // 16 rows x ld 20 (80B rows, 16B aligned)
#pragma unroll
    for (int i = 0; i < 4; i++)
#pragma unroll
        for (int j = 0; j < 2; j++) {
            wmma::store_matrix_sync(stage, c[i][j], 20, wmma::mem_row_major);
            __syncwarp();
            int r  = lane >> 1;
            int cs = (lane & 1) << 3;
            int gr = bm + wrow * WM + i * 16 + r;
            int gc = bn + wcol * WN + j * 16 + cs;
            float4 v0 = *reinterpret_cast<float4*>(&stage[r * 20 + cs]);
            float4 v1 = *reinterpret_cast<float4*>(&stage[r * 20 + cs + 4]);
            if (bias) {
                float4 b0 = *reinterpret_cast<const float4*>(&bias[gc]);
                float4 b1 = *reinterpret_cast<const float4*>(&bias[gc + 4]);
                v0.x += b0.x; v0.y += b0.y; v0.z += b0.z; v0.w += b0.w;
                v1.x += b1.x; v1.y += b1.y; v1.z += b1.z; v1.w += b1.w;
            }
            *reinterpret_cast<float4*>(&C[(size_t)gr * ldc + gc])     = v0;
            *reinterpret_cast<float4*>(&C[(size_t)gr * ldc + gc + 4]) = v1;
            __syncwarp();
        }
}

// b'[j] = sum_k b_qkv[2048+k] * w_proj[k, j] + b_proj[j]
__global__ void bias_combine(const float* __restrict__ bq,
                             const float* __restrict__ wp,
                             const float* __restrict__ bp,
                             float* __restrict__ out)
{
    int j = blockIdx.x * blockDim.x + threadIdx.x;
    float s = bp[j];
    for (int k = 0; k < DIMC; k++)
        s = fmaf(bq[2 * DIMC + k], wp[k * DIMC + j], s);
    out[j] = s;
}

extern "C" void kernel_launch(void* const* d_in, const int* in_sizes, int n_in,
                              void* d_out, int out_size)
{
    const float* x      = (const float*)d_in[0];
    const float* w_qkv  = (const float*)d_in[1];
    const float* b_qkv  = (const float*)d_in[2];
    const float* w_proj = (const float*)d_in[3];
    const float* b_proj = (const float*)d_in[4];
    float* out = (float*)d_out;

    float *wc = nullptr, *bc = nullptr;
    cudaGetSymbolAddress((void**)&wc, g_wc);
    cudaGetSymbolAddress((void**)&bc, g_bc);

    // 1) W' = Wv @ Wproj   (Wv = columns [2048,3072) of w_qkv, lda = 3072)
    gemm_tf32<<<dim3(DIMC / BN, DIMC / BM), 256>>>(
        w_qkv + 2 * DIMC, 3 * DIMC, w_proj, DIMC, wc, DIMC, nullptr, DIMC);

    // 2) combined bias
    bias_combine<<<DIMC / 256, 256>>>(b_qkv, w_proj, b_proj, bc);

    // 3) out = x @ W' + b'
    gemm_tf32<<<dim3(DIMC / BN, MX / BM), 256>>>(
        x, DIMC, wc, DIMC, out, DIMC, bc, DIMC);
}